// round 1
// baseline (speedup 1.0000x reference)
#include <cuda_runtime.h>

// ChamferDistance: B=8, N=M=8192, D=3
// d(i,j) = |x_i|^2 + |y_j|^2 - 2 x_i.y_j
// out = mean_j min_i d + mean_i min_j d
//
// Strategy: min_j (|y_j|^2 - 2 x_i.y_j) + |x_i|^2  (x-norm constant under min)
// -> 4 fma-pipe ops + 1 alu min per pair. Both directions in one kernel.

#define TPB   256
#define RX    2
#define CHUNK (TPB * RX)          // 512 owned points per block
#define PTS   8192
#define BATCH 8
#define TILE  1024
#define CHUNKS_PER_BATCH (PTS / CHUNK)                  // 16
#define BLOCKS_PER_DIR   (BATCH * CHUNKS_PER_BATCH)     // 128
#define NBLOCKS          (2 * BLOCKS_PER_DIR)           // 256

__device__ float g_part[NBLOCKS];

__global__ __launch_bounds__(TPB)
void chamfer_pass_kernel(const float* __restrict__ x, const float* __restrict__ y) {
    const int bid = blockIdx.x;
    const float* own;
    const float* opp;
    int lbid;
    if (bid < BLOCKS_PER_DIR) { own = x; opp = y; lbid = bid; }
    else                      { own = y; opp = x; lbid = bid - BLOCKS_PER_DIR; }

    const int batch = lbid / CHUNKS_PER_BATCH;
    const int chunk = lbid % CHUNKS_PER_BATCH;
    const float* __restrict__ ownb = own + (size_t)batch * PTS * 3;
    const float* __restrict__ oppb = opp + (size_t)batch * PTS * 3;

    __shared__ float sy0[TILE];
    __shared__ float sy1[TILE];
    __shared__ float sy2[TILE];
    __shared__ float syn[TILE];

    const int tid = threadIdx.x;

    // Load owned points into registers
    float x0[RX], x1[RX], x2[RX], mn[RX];
#pragma unroll
    for (int r = 0; r < RX; r++) {
        int i = chunk * CHUNK + r * TPB + tid;
        x0[r] = ownb[i * 3 + 0];
        x1[r] = ownb[i * 3 + 1];
        x2[r] = ownb[i * 3 + 2];
        mn[r] = 3.4e38f;
    }

    for (int t0 = 0; t0 < PTS; t0 += TILE) {
        __syncthreads();
#pragma unroll
        for (int j = tid; j < TILE; j += TPB) {
            float a = oppb[(t0 + j) * 3 + 0];
            float b = oppb[(t0 + j) * 3 + 1];
            float c = oppb[(t0 + j) * 3 + 2];
            sy0[j] = a;
            sy1[j] = b;
            sy2[j] = c;
            syn[j] = fmaf(a, a, fmaf(b, b, c * c));
        }
        __syncthreads();

#pragma unroll 8
        for (int j = 0; j < TILE; ++j) {
            float a = sy0[j];
            float b = sy1[j];
            float c = sy2[j];
            float n = syn[j];
#pragma unroll
            for (int r = 0; r < RX; ++r) {
                float dot = fmaf(x0[r], a, fmaf(x1[r], b, x2[r] * c));
                mn[r] = fminf(mn[r], fmaf(dot, -2.0f, n));
            }
        }
    }

    // per-thread sum of (min_t + |x|^2)
    float s = 0.0f;
#pragma unroll
    for (int r = 0; r < RX; r++) {
        float xn = fmaf(x0[r], x0[r], fmaf(x1[r], x1[r], x2[r] * x2[r]));
        s += mn[r] + xn;
    }

    // deterministic block tree reduction
    __shared__ float red[TPB];
    red[tid] = s;
    __syncthreads();
#pragma unroll
    for (int off = TPB / 2; off > 0; off >>= 1) {
        if (tid < off) red[tid] += red[tid + off];
        __syncthreads();
    }
    if (tid == 0) g_part[bid] = red[0];
}

__global__ __launch_bounds__(NBLOCKS)
void chamfer_final_kernel(float* __restrict__ out) {
    __shared__ float red[NBLOCKS];
    const int tid = threadIdx.x;
    red[tid] = g_part[tid];
    __syncthreads();
#pragma unroll
    for (int off = NBLOCKS / 2; off > 0; off >>= 1) {
        if (tid < off) red[tid] += red[tid + off];
        __syncthreads();
    }
    if (tid == 0) out[0] = red[0] / (float)(BATCH * PTS);
}

extern "C" void kernel_launch(void* const* d_in, const int* in_sizes, int n_in,
                              void* d_out, int out_size) {
    const float* x = (const float*)d_in[0];
    const float* y = (const float*)d_in[1];
    float* out = (float*)d_out;

    chamfer_pass_kernel<<<NBLOCKS, TPB>>>(x, y);
    chamfer_final_kernel<<<1, NBLOCKS>>>(out);
}

// round 2
// speedup vs baseline: 1.1611x; 1.1611x over previous
#include <cuda_runtime.h>
#include <cstdint>

// ChamferDistance: B=8, N=M=8192, D=3
// d(i,j) = |x_i|^2 + |y_j|^2 - 2 x_i.y_j
// out = mean_j min_i d + mean_i min_j d
//
// min_j d = min_j (n_j + x . y'_j) + |x_i|^2, with y' = -2y precomputed in the
// shared-tile fill. Inner loop: 3 packed fma.rn.f32x2 per TWO opposing points
// -> 1.5 FFMA2-slots per pair (vs 4 scalar FFMA in round 1).

#define TPB   256
#define RX    2
#define CHUNK (TPB * RX)          // 512 owned points per block
#define PTS   8192
#define BATCH 8
#define TILE  1024
#define JP    (TILE / 2)          // j-pairs per tile
#define CHUNKS_PER_BATCH (PTS / CHUNK)                  // 16
#define BLOCKS_PER_DIR   (BATCH * CHUNKS_PER_BATCH)     // 128
#define NBLOCKS          (2 * BLOCKS_PER_DIR)           // 256

__device__ float g_part[NBLOCKS];

#define PACK_F32X2(out, lo, hi) \
    asm("mov.b64 %0, {%1, %2};" : "=l"(out) : "f"(lo), "f"(hi))

#define UNPACK_F32X2(lo, hi, in) \
    asm("mov.b64 {%0, %1}, %2;" : "=f"(lo), "=f"(hi) : "l"(in))

#define FMA_F32X2(d, a, b, c) \
    asm("fma.rn.f32x2 %0, %1, %2, %3;" : "=l"(d) : "l"(a), "l"(b), "l"(c))

__global__ __launch_bounds__(TPB)
void chamfer_pass_kernel(const float* __restrict__ x, const float* __restrict__ y) {
    const int bid = blockIdx.x;
    const float* own;
    const float* opp;
    int lbid;
    if (bid < BLOCKS_PER_DIR) { own = x; opp = y; lbid = bid; }
    else                      { own = y; opp = x; lbid = bid - BLOCKS_PER_DIR; }

    const int batch = lbid / CHUNKS_PER_BATCH;
    const int chunk = lbid % CHUNKS_PER_BATCH;
    const float* __restrict__ ownb = own + (size_t)batch * PTS * 3;
    const float* __restrict__ oppb = opp + (size_t)batch * PTS * 3;

    // Per j-pair: sAB = (-2a0,-2a1,-2b0,-2b1), sCN = (-2c0,-2c1,n0,n1)
    __shared__ __align__(16) float4 sAB[JP];
    __shared__ __align__(16) float4 sCN[JP];

    const int tid = threadIdx.x;

    // Owned points: pre-broadcast each coordinate into both f32x2 lanes.
    float x0[RX], x1[RX], x2[RX];
    unsigned long long xa[RX], xb[RX], xc[RX];
    float mnl[RX], mnh[RX];
#pragma unroll
    for (int r = 0; r < RX; r++) {
        int i = chunk * CHUNK + r * TPB + tid;
        x0[r] = ownb[i * 3 + 0];
        x1[r] = ownb[i * 3 + 1];
        x2[r] = ownb[i * 3 + 2];
        PACK_F32X2(xa[r], x0[r], x0[r]);
        PACK_F32X2(xb[r], x1[r], x1[r]);
        PACK_F32X2(xc[r], x2[r], x2[r]);
        mnl[r] = 3.4e38f;
        mnh[r] = 3.4e38f;
    }

    for (int t0 = 0; t0 < PTS; t0 += TILE) {
        __syncthreads();
#pragma unroll
        for (int jj = tid; jj < TILE; jj += TPB) {
            float a = oppb[(t0 + jj) * 3 + 0];
            float b = oppb[(t0 + jj) * 3 + 1];
            float c = oppb[(t0 + jj) * 3 + 2];
            float n = fmaf(a, a, fmaf(b, b, c * c));
            int   jp = jj >> 1;
            int   lane = jj & 1;
            float* pab = (float*)&sAB[jp];
            float* pcn = (float*)&sCN[jp];
            pab[lane + 0] = -2.0f * a;
            pab[lane + 2] = -2.0f * b;
            pcn[lane + 0] = -2.0f * c;
            pcn[lane + 2] = n;
        }
        __syncthreads();

#pragma unroll 8
        for (int jp = 0; jp < JP; ++jp) {
            float4 ab = sAB[jp];
            float4 cn = sCN[jp];
            unsigned long long a2, b2, c2, n2;
            PACK_F32X2(a2, ab.x, ab.y);
            PACK_F32X2(b2, ab.z, ab.w);
            PACK_F32X2(c2, cn.x, cn.y);
            PACK_F32X2(n2, cn.z, cn.w);
#pragma unroll
            for (int r = 0; r < RX; ++r) {
                unsigned long long t;
                FMA_F32X2(t, xc[r], c2, n2);
                FMA_F32X2(t, xb[r], b2, t);
                FMA_F32X2(t, xa[r], a2, t);
                float lo, hi;
                UNPACK_F32X2(lo, hi, t);
                mnl[r] = fminf(mnl[r], lo);
                mnh[r] = fminf(mnh[r], hi);
            }
        }
    }

    // per-thread sum of (min_j + |x|^2)
    float s = 0.0f;
#pragma unroll
    for (int r = 0; r < RX; r++) {
        float xn = fmaf(x0[r], x0[r], fmaf(x1[r], x1[r], x2[r] * x2[r]));
        s += fminf(mnl[r], mnh[r]) + xn;
    }

    // deterministic block tree reduction
    __shared__ float red[TPB];
    red[tid] = s;
    __syncthreads();
#pragma unroll
    for (int off = TPB / 2; off > 0; off >>= 1) {
        if (tid < off) red[tid] += red[tid + off];
        __syncthreads();
    }
    if (tid == 0) g_part[bid] = red[0];
}

__global__ __launch_bounds__(NBLOCKS)
void chamfer_final_kernel(float* __restrict__ out) {
    __shared__ float red[NBLOCKS];
    const int tid = threadIdx.x;
    red[tid] = g_part[tid];
    __syncthreads();
#pragma unroll
    for (int off = NBLOCKS / 2; off > 0; off >>= 1) {
        if (tid < off) red[tid] += red[tid + off];
        __syncthreads();
    }
    if (tid == 0) out[0] = red[0] / (float)(BATCH * PTS);
}

extern "C" void kernel_launch(void* const* d_in, const int* in_sizes, int n_in,
                              void* d_out, int out_size) {
    const float* x = (const float*)d_in[0];
    const float* y = (const float*)d_in[1];
    float* out = (float*)d_out;

    chamfer_pass_kernel<<<NBLOCKS, TPB>>>(x, y);
    chamfer_final_kernel<<<1, NBLOCKS>>>(out);
}